// round 6
// baseline (speedup 1.0000x reference)
#include <cuda_runtime.h>
#include <cstdint>

#define Bn 8
#define Cn 21
#define Hn 512
#define Wn 512
#define HWn (Hn * Wn)
#define Pn (Bn * HWn)      // 2097152 pixels
#define NBINS 65536

// Packed histogram: low 32 bits = count, high 32 bits = fg count.
__device__ unsigned long long g_hist[Cn * NBINS];
__device__ double g_class_loss[Cn];

// ---------------------------------------------------------------------------
// Kernel 0: zero scratch + output
// ---------------------------------------------------------------------------
__global__ void zero_kernel(float* d_out) {
    int idx = blockIdx.x * blockDim.x + threadIdx.x;
    int stride = gridDim.x * blockDim.x;
    const int total = Cn * NBINS;
    for (int i = idx; i < total; i += stride) g_hist[i] = 0ull;
    if (idx < Cn) g_class_loss[idx] = 0.0;
    if (idx == 0) *d_out = 0.0f;
}

// ---------------------------------------------------------------------------
// Kernel 1: per-pixel softmax + per-class error binning (one u64 RED each)
// targets are int32 (JAX without x64 downcasts int64 -> int32).
// ---------------------------------------------------------------------------
__global__ void __launch_bounds__(256) hist_kernel(
    const float* __restrict__ x, const int* __restrict__ labels) {
    int p = blockIdx.x * blockDim.x + threadIdx.x;
    if (p >= Pn) return;
    int b = p >> 18;            // p / HWn  (HWn = 262144 = 2^18)
    int pix = p & (HWn - 1);
    const float* base = x + (size_t)b * Cn * HWn + pix;

    float v[Cn];
    float m = -1e30f;
#pragma unroll
    for (int c = 0; c < Cn; c++) {
        v[c] = base[(size_t)c * HWn];
        m = fmaxf(m, v[c]);
    }
    float s = 0.0f;
#pragma unroll
    for (int c = 0; c < Cn; c++) {
        v[c] = __expf(v[c] - m);
        s += v[c];
    }
    float inv = 1.0f / s;
    int lab = labels[p];
    // defensive clamp: label only selects the fg bit, never an address
    if (lab < 0 || lab >= Cn) lab = -1;

#pragma unroll
    for (int c = 0; c < Cn; c++) {
        float pr = v[c] * inv;
        int fg = (c == lab) ? 1 : 0;
        float e = fg ? (1.0f - pr) : pr;
        e = fminf(fmaxf(e, 0.0f), 1.0f);
        int q = (int)(e * 65536.0f);
        q = min(q, NBINS - 1);
        unsigned long long add = 1ull | ((unsigned long long)fg << 32);
        atomicAdd(&g_hist[c * NBINS + q], add);
    }
}

// ---------------------------------------------------------------------------
// Kernel 2: per-class descending scan over bins + Lovasz telescoped sum
// One block per class, 1024 threads.
// ---------------------------------------------------------------------------
__global__ void __launch_bounds__(1024) finalize_kernel() {
    const int c = blockIdx.x;
    const unsigned long long* hist = g_hist + (size_t)c * NBINS;
    const int tid = threadIdx.x;
    const int lane = tid & 31;
    const int warp = tid >> 5;
    const int NW = 1024 / 32;   // 32 warps

    __shared__ unsigned long long s_warp[32];
    __shared__ unsigned int s_G;
    __shared__ double s_red[32];

    // ---- Phase 1: total foreground count G for this class ----
    unsigned long long tot = 0;
    for (int i = tid; i < NBINS; i += 1024) tot += (hist[i] >> 32);
    for (int o = 16; o; o >>= 1) tot += __shfl_down_sync(0xffffffffu, tot, o);
    if (lane == 0) s_warp[warp] = tot;
    __syncthreads();
    if (warp == 0) {
        unsigned long long t = (lane < NW) ? s_warp[lane] : 0ull;
        for (int o = 16; o; o >>= 1) t += __shfl_down_sync(0xffffffffu, t, o);
        if (lane == 0) s_G = (unsigned int)t;
    }
    __syncthreads();
    const long long G = (long long)s_G;

    // ---- Phase 2: descending-bin segmented inclusive scan + contribution ----
    unsigned long long carry = 0;   // packed cumulative (n | s<<32)
    double acc = 0.0;
    const float binw = 1.0f / 65536.0f;

    for (int chunk = 0; chunk < NBINS; chunk += 1024) {
        int idx = chunk + tid;
        int bin = NBINS - 1 - idx;          // descending error order
        unsigned long long h = hist[bin];

        // inclusive scan of packed (cnt, fg) — halves never cross-carry
        // (cumulative counts < 2^22 per half)
        unsigned long long v = h;
        for (int o = 1; o < 32; o <<= 1) {
            unsigned long long u = __shfl_up_sync(0xffffffffu, v, o);
            if (lane >= o) v += u;
        }
        if (lane == 31) s_warp[warp] = v;
        __syncthreads();
        if (warp == 0) {
            unsigned long long w = (lane < NW) ? s_warp[lane] : 0ull;
            for (int o = 1; o < 32; o <<= 1) {
                unsigned long long u2 = __shfl_up_sync(0xffffffffu, w, o);
                if (lane >= o) w += u2;
            }
            if (lane < NW) s_warp[lane] = w;
        }
        __syncthreads();
        unsigned long long warpoff = (warp > 0) ? s_warp[warp - 1] : 0ull;
        unsigned long long incl = carry + warpoff + v;
        unsigned long long chunk_total = s_warp[NW - 1];

        unsigned int cnt = (unsigned int)(h & 0xffffffffu);
        if (cnt) {
            unsigned int fg = (unsigned int)(h >> 32);
            long long n  = (long long)(unsigned int)(incl & 0xffffffffu);
            long long ss = (long long)(unsigned int)(incl >> 32);
            long long np = n - (long long)cnt;
            long long sp = ss - (long long)fg;
            long long u1 = G + n - ss;       // union after this bin
            long long u0 = G + np - sp;      // union before this bin
            float dJ;
            if (u0 == 0) {
                // only possible when G==0 and this is the first nonempty bin:
                // J_prev = 0, J = 1 - 0/u1 = 1
                dJ = 1.0f;
            } else {
                // exact integer cross-multiplication avoids cancellation
                long long num = (G - sp) * u1 - (G - ss) * u0;
                dJ = (float)num / ((float)u1 * (float)u0);
            }
            float e_mid = ((float)bin + 0.5f) * binw;
            acc += (double)(e_mid * dJ);
        }
        carry += chunk_total;
        __syncthreads();   // protect s_warp for next chunk
    }

    // ---- reduce acc across block ----
    for (int o = 16; o; o >>= 1) acc += __shfl_down_sync(0xffffffffu, acc, o);
    if (lane == 0) s_red[warp] = acc;
    __syncthreads();
    if (warp == 0) {
        double a = (lane < NW) ? s_red[lane] : 0.0;
        for (int o = 16; o; o >>= 1) a += __shfl_down_sync(0xffffffffu, a, o);
        if (lane == 0) g_class_loss[c] = a;
    }
}

// ---------------------------------------------------------------------------
// Kernel 3: deterministic final mean over classes
// ---------------------------------------------------------------------------
__global__ void sum_kernel(float* d_out) {
    if (threadIdx.x == 0 && blockIdx.x == 0) {
        double s = 0.0;
        for (int c = 0; c < Cn; c++) s += g_class_loss[c];
        *d_out = (float)(s / (double)Cn);   // LOSS_WEIGHT = 1.0
    }
}

// ---------------------------------------------------------------------------
extern "C" void kernel_launch(void* const* d_in, const int* in_sizes, int n_in,
                              void* d_out, int out_size) {
    const float* inputs = (const float*)d_in[0];   // [8,21,512,512] f32
    const int* targets = (const int*)d_in[1];      // [8,512,512] int32
    float* out = (float*)d_out;

    zero_kernel<<<2048, 256>>>(out);
    hist_kernel<<<(Pn + 255) / 256, 256>>>(inputs, targets);
    finalize_kernel<<<Cn, 1024>>>();
    sum_kernel<<<1, 32>>>(out);
}

// round 7
// speedup vs baseline: 1.0928x; 1.0928x over previous
#include <cuda_runtime.h>
#include <cstdint>

#define Bn 8
#define Cn 21
#define Hn 512
#define Wn 512
#define HWn (Hn * Wn)
#define Pn (Bn * HWn)       // 2097152 = 2^21 pixels
#define NB 512              // error bins
#define NWARP 8             // warps per hist block
#define HIST_SMEM (NWARP * Cn * NB * 2)   // u16 per-warp hists = 172032 B

__device__ unsigned g_cnthist[Cn * NB];   // total count per (class,bin)
__device__ unsigned g_fghist[Cn * NB];    // fg count per (class,bin)
__device__ double g_class_loss[Cn];

// ---------------------------------------------------------------------------
// Kernel 0: zero scratch + output (tiny: 86 KB)
// ---------------------------------------------------------------------------
__global__ void zero_kernel(float* d_out) {
    int idx = blockIdx.x * blockDim.x + threadIdx.x;
    int stride = gridDim.x * blockDim.x;
    for (int i = idx; i < Cn * NB; i += stride) {
        g_cnthist[i] = 0u;
        g_fghist[i] = 0u;
    }
    if (idx < Cn) g_class_loss[idx] = 0.0;
    if (idx == 0) *d_out = 0.0f;
}

// ---------------------------------------------------------------------------
// Kernel 1: softmax + per-warp ATOMIC-FREE smem histograms.
// grid=128 blocks x 256 threads x 64 px/thread = 2^21 px exactly (all lanes
// always valid -> full-mask warp ops). Per-warp u16 hist, collisions within
// a warp resolved via __match_any + leader popc add. fg (1/pixel) goes
// straight to a small global RED hist.
// ---------------------------------------------------------------------------
__global__ void __launch_bounds__(256) hist_kernel(
    const float* __restrict__ x, const int* __restrict__ labels) {
    extern __shared__ unsigned short sh[];          // [NWARP][Cn*NB]
    const int tid = threadIdx.x;
    const int lane = tid & 31;
    const int w = tid >> 5;
    unsigned short* mine = sh + w * (Cn * NB);

    // zero smem (172032 B = 43008 u32)
    for (int i = tid; i < HIST_SMEM / 4; i += 256)
        ((unsigned*)sh)[i] = 0u;
    __syncthreads();

    const int base_p = blockIdx.x * 16384 + tid;
    const unsigned lower = (1u << lane) - 1u;

    for (int it = 0; it < 64; it++) {
        int p = base_p + it * 256;
        int b = p >> 18;                 // / HWn (2^18)
        int pix = p & (HWn - 1);
        const float* xb = x + (size_t)b * Cn * HWn + pix;

        float v[Cn];
        float m = -1e30f;
#pragma unroll
        for (int c = 0; c < Cn; c++) {
            v[c] = xb[(size_t)c * HWn];
            m = fmaxf(m, v[c]);
        }
        float s = 0.0f;
#pragma unroll
        for (int c = 0; c < Cn; c++) {
            v[c] = __expf(v[c] - m);
            s += v[c];
        }
        float inv = 1.0f / s;
        int lab = labels[p];
        if (lab < 0 || lab >= Cn) lab = -1;   // address-safety

#pragma unroll
        for (int c = 0; c < Cn; c++) {
            float pr = v[c] * inv;
            bool fg = (c == lab);
            float e = fg ? (1.0f - pr) : pr;
            e = fminf(fmaxf(e, 0.0f), 1.0f);
            int q = (int)(e * (float)NB);
            q = min(q, NB - 1);

            unsigned mask = __match_any_sync(0xffffffffu, q);
            if (fg) atomicAdd(&g_fghist[c * NB + q], 1u);   // rare: 1/pixel
            if ((mask & lower) == 0u) {                     // group leader
                mine[c * NB + q] =
                    (unsigned short)(mine[c * NB + q] + (unsigned)__popc(mask));
            }
        }
    }
    __syncthreads();

    // flush: sum the 8 warp hists, one u32 RED per nonzero (class,bin)
    for (int slot = tid; slot < Cn * NB; slot += 256) {
        unsigned t = 0;
#pragma unroll
        for (int w2 = 0; w2 < NWARP; w2++)
            t += sh[w2 * (Cn * NB) + slot];
        if (t) atomicAdd(&g_cnthist[slot], t);
    }
}

// ---------------------------------------------------------------------------
// Kernel 2: per-class single-chunk descending scan over 512 bins + Lovasz sum.
// One block per class, 512 threads (one bin each).
// ---------------------------------------------------------------------------
__global__ void __launch_bounds__(512) finalize_kernel() {
    const int c = blockIdx.x;
    const int tid = threadIdx.x;
    const int lane = tid & 31;
    const int warp = tid >> 5;
    const int NW = 512 / 32;   // 16 warps

    __shared__ unsigned long long s_warp[16];
    __shared__ double s_red[16];

    const int bin = NB - 1 - tid;     // descending error order
    unsigned cnt = g_cnthist[c * NB + bin];
    unsigned fgc = g_fghist[c * NB + bin];
    unsigned long long h = (unsigned long long)cnt | ((unsigned long long)fgc << 32);

    // inclusive scan of packed (cnt | fg<<32): halves never cross-carry
    unsigned long long v = h;
    for (int o = 1; o < 32; o <<= 1) {
        unsigned long long u = __shfl_up_sync(0xffffffffu, v, o);
        if (lane >= o) v += u;
    }
    if (lane == 31) s_warp[warp] = v;
    __syncthreads();
    if (warp == 0) {
        unsigned long long wv = (lane < NW) ? s_warp[lane] : 0ull;
        for (int o = 1; o < 32; o <<= 1) {
            unsigned long long u2 = __shfl_up_sync(0xffffffffu, wv, o);
            if (lane >= o) wv += u2;
        }
        if (lane < NW) s_warp[lane] = wv;
    }
    __syncthreads();
    unsigned long long incl = v + (warp > 0 ? s_warp[warp - 1] : 0ull);
    unsigned long long total = s_warp[NW - 1];
    const long long G = (long long)(unsigned)(total >> 32);

    double acc = 0.0;
    if (cnt) {
        long long n  = (long long)(unsigned)(incl & 0xffffffffu);
        long long ss = (long long)(unsigned)(incl >> 32);
        long long np = n - (long long)cnt;
        long long sp = ss - (long long)fgc;
        long long u1 = G + n - ss;       // union after this bin
        long long u0 = G + np - sp;      // union before this bin
        float dJ;
        if (u0 == 0) {
            dJ = 1.0f;                   // G==0, first nonempty bin: J 0 -> 1
        } else {
            long long num = (G - sp) * u1 - (G - ss) * u0;  // exact int64
            dJ = (float)num / ((float)u1 * (float)u0);
        }
        float e_mid = ((float)bin + 0.5f) * (1.0f / (float)NB);
        acc = (double)(e_mid * dJ);
    }

    // block reduce (doubles)
    for (int o = 16; o; o >>= 1) acc += __shfl_down_sync(0xffffffffu, acc, o);
    if (lane == 0) s_red[warp] = acc;
    __syncthreads();
    if (warp == 0) {
        double a = (lane < NW) ? s_red[lane] : 0.0;
        for (int o = 16; o; o >>= 1) a += __shfl_down_sync(0xffffffffu, a, o);
        if (lane == 0) g_class_loss[c] = a;
    }
}

// ---------------------------------------------------------------------------
// Kernel 3: deterministic final mean over classes
// ---------------------------------------------------------------------------
__global__ void sum_kernel(float* d_out) {
    if (threadIdx.x == 0 && blockIdx.x == 0) {
        double s = 0.0;
        for (int c = 0; c < Cn; c++) s += g_class_loss[c];
        *d_out = (float)(s / (double)Cn);   // LOSS_WEIGHT = 1.0
    }
}

// ---------------------------------------------------------------------------
extern "C" void kernel_launch(void* const* d_in, const int* in_sizes, int n_in,
                              void* d_out, int out_size) {
    const float* inputs = (const float*)d_in[0];   // [8,21,512,512] f32
    const int* targets = (const int*)d_in[1];      // [8,512,512] int32
    float* out = (float*)d_out;

    static bool attr_set = false;
    if (!attr_set) {
        cudaFuncSetAttribute(hist_kernel,
                             cudaFuncAttributeMaxDynamicSharedMemorySize,
                             HIST_SMEM);
        attr_set = true;
    }

    zero_kernel<<<42, 256>>>(out);
    hist_kernel<<<128, 256, HIST_SMEM>>>(inputs, targets);
    finalize_kernel<<<Cn, 512>>>();
    sum_kernel<<<1, 32>>>(out);
}

// round 8
// speedup vs baseline: 2.1983x; 2.0116x over previous
#include <cuda_runtime.h>
#include <cstdint>

#define Bn 8
#define Cn 21
#define Hn 512
#define Wn 512
#define HWn (Hn * Wn)
#define Pn (Bn * HWn)       // 2097152 = 2^21 pixels
#define NB 128              // error bins
#define NWARP 8             // warps per hist block
#define HBLK 512            // hist grid blocks

__device__ unsigned g_cnthist[Cn * NB];   // total count per (class,bin)
__device__ unsigned g_fghist[Cn * NB];    // fg count per (class,bin)
__device__ double g_class_loss[Cn];

// ---------------------------------------------------------------------------
// Kernel 0: zero scratch + output (tiny)
// ---------------------------------------------------------------------------
__global__ void zero_kernel(float* d_out) {
    int idx = blockIdx.x * blockDim.x + threadIdx.x;
    int stride = gridDim.x * blockDim.x;
    for (int i = idx; i < Cn * NB; i += stride) {
        g_cnthist[i] = 0u;
        g_fghist[i] = 0u;
    }
    if (idx < Cn) g_class_loss[idx] = 0.0;
    if (idx == 0) *d_out = 0.0f;
}

// ---------------------------------------------------------------------------
// Kernel 1: softmax + per-warp ATOMIC-FREE u16 smem histograms.
// 512 blocks x 256 threads; each thread: 8 iters x 2 pixels (float2/int2).
// 42KB static smem -> 3 CTAs/SM (launch_bounds), 6 warps/SMSP.
// Branchless inner loop; one global fg RED per pixel (outside class loop).
// ---------------------------------------------------------------------------
__global__ void __launch_bounds__(256, 3) hist_kernel(
    const float* __restrict__ x, const int* __restrict__ labels) {
    __shared__ unsigned short sh[NWARP][Cn * NB];     // 43008 B
    const int tid = threadIdx.x;
    const int lane = tid & 31;
    const int w = tid >> 5;
    unsigned short* mine = sh[w];

    // zero smem
    for (int i = tid; i < (NWARP * Cn * NB) / 2; i += 256)
        ((unsigned*)sh)[i] = 0u;
    __syncthreads();

    const unsigned lower = (1u << lane) - 1u;

    for (int it = 0; it < 8; it++) {
        int pair = blockIdx.x * 2048 + it * 256 + tid;   // < 2^20
        int p = pair << 1;
        int b = p >> 18;                  // / HWn (2^18)
        int pix = p & (HWn - 1);
        const float2* xb = (const float2*)(x + (size_t)b * Cn * HWn + pix);

        float2 v[Cn];
        float mx = -1e30f, my = -1e30f;
#pragma unroll
        for (int c = 0; c < Cn; c++) {
            v[c] = xb[c * (HWn / 2)];
            mx = fmaxf(mx, v[c].x);
            my = fmaxf(my, v[c].y);
        }
        float sx = 0.0f, sy = 0.0f;
#pragma unroll
        for (int c = 0; c < Cn; c++) {
            v[c].x = __expf(v[c].x - mx);
            v[c].y = __expf(v[c].y - my);
            sx += v[c].x;
            sy += v[c].y;
        }
        float invx = 1.0f / sx, invy = 1.0f / sy;

        int2 lab2 = ((const int2*)labels)[pair];
        int labx = lab2.x, laby = lab2.y;
        if (labx < 0 || labx >= Cn) labx = -1;   // address-safety
        if (laby < 0 || laby >= Cn) laby = -1;

        int qlx = 0, qly = 0;
#pragma unroll
        for (int c = 0; c < Cn; c++) {
            // pixel x
            {
                float pr = v[c].x * invx;
                bool fg = (c == labx);
                float e = fg ? (1.0f - pr) : pr;      // e in [0,1]
                int q = min((int)(e * (float)NB), NB - 1);
                if (fg) qlx = q;                      // predicated select
                unsigned mk = __match_any_sync(0xffffffffu, q);
                if ((mk & lower) == 0u)               // group leader
                    mine[c * NB + q] =
                        (unsigned short)(mine[c * NB + q] + (unsigned)__popc(mk));
            }
            // pixel y
            {
                float pr = v[c].y * invy;
                bool fg = (c == laby);
                float e = fg ? (1.0f - pr) : pr;
                int q = min((int)(e * (float)NB), NB - 1);
                if (fg) qly = q;
                unsigned mk = __match_any_sync(0xffffffffu, q);
                if ((mk & lower) == 0u)
                    mine[c * NB + q] =
                        (unsigned short)(mine[c * NB + q] + (unsigned)__popc(mk));
            }
        }
        if (labx >= 0) atomicAdd(&g_fghist[labx * NB + qlx], 1u);
        if (laby >= 0) atomicAdd(&g_fghist[laby * NB + qly], 1u);
    }
    __syncthreads();

    // flush: sum the 8 warp hists, one u32 RED per nonzero (class,bin)
    for (int slot = tid; slot < Cn * NB; slot += 256) {
        unsigned t = 0;
#pragma unroll
        for (int w2 = 0; w2 < NWARP; w2++)
            t += sh[w2][slot];
        if (t) atomicAdd(&g_cnthist[slot], t);
    }
}

// ---------------------------------------------------------------------------
// Kernel 2: per-class descending scan over 128 bins + Lovasz telescoped sum.
// One block per class, 128 threads (one bin each), 4 warps.
// ---------------------------------------------------------------------------
__global__ void __launch_bounds__(128) finalize_kernel() {
    const int c = blockIdx.x;
    const int tid = threadIdx.x;
    const int lane = tid & 31;
    const int warp = tid >> 5;
    const int NW = NB / 32;   // 4 warps

    __shared__ unsigned long long s_warp[NB / 32];
    __shared__ double s_red[NB / 32];

    const int bin = NB - 1 - tid;     // descending error order
    unsigned cnt = g_cnthist[c * NB + bin];
    unsigned fgc = g_fghist[c * NB + bin];
    unsigned long long h = (unsigned long long)cnt | ((unsigned long long)fgc << 32);

    // inclusive scan of packed (cnt | fg<<32): halves never cross-carry
    unsigned long long v = h;
    for (int o = 1; o < 32; o <<= 1) {
        unsigned long long u = __shfl_up_sync(0xffffffffu, v, o);
        if (lane >= o) v += u;
    }
    if (lane == 31) s_warp[warp] = v;
    __syncthreads();
    if (warp == 0) {
        unsigned long long wv = (lane < NW) ? s_warp[lane] : 0ull;
        for (int o = 1; o < NW; o <<= 1) {
            unsigned long long u2 = __shfl_up_sync(0xffffffffu, wv, o);
            if (lane >= o) wv += u2;
        }
        if (lane < NW) s_warp[lane] = wv;
    }
    __syncthreads();
    unsigned long long incl = v + (warp > 0 ? s_warp[warp - 1] : 0ull);
    unsigned long long total = s_warp[NW - 1];
    const long long G = (long long)(unsigned)(total >> 32);

    double acc = 0.0;
    if (cnt) {
        long long n  = (long long)(unsigned)(incl & 0xffffffffu);
        long long ss = (long long)(unsigned)(incl >> 32);
        long long np = n - (long long)cnt;
        long long sp = ss - (long long)fgc;
        long long u1 = G + n - ss;       // union after this bin
        long long u0 = G + np - sp;      // union before this bin
        float dJ;
        if (u0 == 0) {
            dJ = 1.0f;                   // G==0, first nonempty bin: J 0 -> 1
        } else {
            long long num = (G - sp) * u1 - (G - ss) * u0;  // exact int64
            dJ = (float)num / ((float)u1 * (float)u0);
        }
        float e_mid = ((float)bin + 0.5f) * (1.0f / (float)NB);
        acc = (double)(e_mid * dJ);
    }

    // block reduce (doubles)
    for (int o = 16; o; o >>= 1) acc += __shfl_down_sync(0xffffffffu, acc, o);
    if (lane == 0) s_red[warp] = acc;
    __syncthreads();
    if (warp == 0) {
        double a = (lane < NW) ? s_red[lane] : 0.0;
        for (int o = 2; o; o >>= 1) a += __shfl_down_sync(0xffffffffu, a, o);
        if (lane == 0) g_class_loss[c] = a;
    }
}

// ---------------------------------------------------------------------------
// Kernel 3: deterministic final mean over classes
// ---------------------------------------------------------------------------
__global__ void sum_kernel(float* d_out) {
    if (threadIdx.x == 0 && blockIdx.x == 0) {
        double s = 0.0;
        for (int c = 0; c < Cn; c++) s += g_class_loss[c];
        *d_out = (float)(s / (double)Cn);   // LOSS_WEIGHT = 1.0
    }
}

// ---------------------------------------------------------------------------
extern "C" void kernel_launch(void* const* d_in, const int* in_sizes, int n_in,
                              void* d_out, int out_size) {
    const float* inputs = (const float*)d_in[0];   // [8,21,512,512] f32
    const int* targets = (const int*)d_in[1];      // [8,512,512] int32
    float* out = (float*)d_out;

    zero_kernel<<<21, 128>>>(out);
    hist_kernel<<<HBLK, 256>>>(inputs, targets);
    finalize_kernel<<<Cn, NB>>>();
    sum_kernel<<<1, 32>>>(out);
}

// round 9
// speedup vs baseline: 2.5198x; 1.1463x over previous
#include <cuda_runtime.h>
#include <cstdint>

#define Bn 8
#define Cn 21
#define Hn 512
#define Wn 512
#define HWn (Hn * Wn)
#define Pn (Bn * HWn)        // 2097152 = 2^21 pixels
#define NB 128               // error bins
#define NWARP 4              // warps per hist block
#define TPB 128
#define HBLK 1024            // hist grid blocks
#define ITERS 16             // pixels per thread
#define WSLOTS (Cn * NB + 32)   // +pad: dummy slot at Cn*NB, rest pads bank shift

__device__ unsigned g_cnthist[Cn * NB];   // total count per (class,bin)
__device__ unsigned g_fghist[Cn * NB];    // fg count per (class,bin)
__device__ double g_class_loss[Cn];

// ---------------------------------------------------------------------------
// Kernel 0: zero scratch + output (tiny)
// ---------------------------------------------------------------------------
__global__ void zero_kernel(float* d_out) {
    int idx = blockIdx.x * blockDim.x + threadIdx.x;
    int stride = gridDim.x * blockDim.x;
    for (int i = idx; i < Cn * NB; i += stride) {
        g_cnthist[i] = 0u;
        g_fghist[i] = 0u;
    }
    if (idx < Cn) g_class_loss[idx] = 0.0;
    if (idx == 0) *d_out = 0.0f;
}

// ---------------------------------------------------------------------------
// Kernel 1: softmax + per-warp atomic-free u16 smem histograms, BRANCHLESS.
// 1024 blocks x 128 threads x 16 px/thread = 2^21 px exactly.
// Non-leader lanes write to a per-warp dummy slot (value irrelevant) so the
// hot loop has zero divergent branches. 21.1KB smem -> 8 CTAs/SM.
// ---------------------------------------------------------------------------
__global__ void __launch_bounds__(TPB, 8) hist_kernel(
    const float* __restrict__ x, const int* __restrict__ labels) {
    __shared__ unsigned short sh[NWARP][WSLOTS];     // 21632 B
    const int tid = threadIdx.x;
    const int lane = tid & 31;
    const int w = tid >> 5;
    unsigned short* mine = sh[w];
    const int DUMMY = Cn * NB;                       // per-warp scratch slot

    // zero smem
    for (int i = tid; i < (NWARP * WSLOTS) / 2; i += TPB)
        ((unsigned*)sh)[i] = 0u;
    __syncthreads();

    const unsigned lower = (1u << lane) - 1u;

    for (int it = 0; it < ITERS; it++) {
        int p = (blockIdx.x * ITERS + it) * TPB + tid;   // < 2^21
        int b = p >> 18;                  // / HWn (2^18)
        int pix = p & (HWn - 1);
        const float* xb = x + (size_t)b * Cn * HWn + pix;

        float v[Cn];
        float m = -1e30f;
#pragma unroll
        for (int c = 0; c < Cn; c++) {
            v[c] = xb[(size_t)c * HWn];
            m = fmaxf(m, v[c]);
        }
        float s = 0.0f;
#pragma unroll
        for (int c = 0; c < Cn; c++) {
            v[c] = __expf(v[c] - m);
            s += v[c];
        }
        float inv = 1.0f / s;

        int lab = labels[p];
        if (lab < 0 || lab >= Cn) lab = -1;   // address-safety

        int qlab = 0;
#pragma unroll
        for (int c = 0; c < Cn; c++) {
            float pr = v[c] * inv;
            bool fg = (c == lab);
            float e = fg ? (1.0f - pr) : pr;          // FSEL, e in [0,1]
            int q = min((int)(e * (float)NB), NB - 1);
            if (fg) qlab = q;                         // predicated select

            unsigned mk = __match_any_sync(0xffffffffu, q);
            bool leader = ((mk & lower) == 0u);
            int slot = leader ? (c * NB + q) : DUMMY; // branchless steer
            unsigned add = (unsigned)__popc(mk);
            mine[slot] = (unsigned short)(mine[slot] + add);
        }
        if (lab >= 0) atomicAdd(&g_fghist[lab * NB + qlab], 1u);
    }
    __syncthreads();

    // flush: sum the 4 warp hists, one u32 RED per nonzero (class,bin)
    for (int slot = tid; slot < Cn * NB; slot += TPB) {
        unsigned t = 0;
#pragma unroll
        for (int w2 = 0; w2 < NWARP; w2++)
            t += sh[w2][slot];
        if (t) atomicAdd(&g_cnthist[slot], t);
    }
}

// ---------------------------------------------------------------------------
// Kernel 2: per-class descending scan over 128 bins + Lovasz telescoped sum.
// One block per class, 128 threads (one bin each), 4 warps.
// ---------------------------------------------------------------------------
__global__ void __launch_bounds__(128) finalize_kernel() {
    const int c = blockIdx.x;
    const int tid = threadIdx.x;
    const int lane = tid & 31;
    const int warp = tid >> 5;
    const int NW = NB / 32;   // 4 warps

    __shared__ unsigned long long s_warp[NB / 32];
    __shared__ double s_red[NB / 32];

    const int bin = NB - 1 - tid;     // descending error order
    unsigned cnt = g_cnthist[c * NB + bin];
    unsigned fgc = g_fghist[c * NB + bin];
    unsigned long long h = (unsigned long long)cnt | ((unsigned long long)fgc << 32);

    // inclusive scan of packed (cnt | fg<<32): halves never cross-carry
    unsigned long long v = h;
    for (int o = 1; o < 32; o <<= 1) {
        unsigned long long u = __shfl_up_sync(0xffffffffu, v, o);
        if (lane >= o) v += u;
    }
    if (lane == 31) s_warp[warp] = v;
    __syncthreads();
    if (warp == 0) {
        unsigned long long wv = (lane < NW) ? s_warp[lane] : 0ull;
        for (int o = 1; o < NW; o <<= 1) {
            unsigned long long u2 = __shfl_up_sync(0xffffffffu, wv, o);
            if (lane >= o) wv += u2;
        }
        if (lane < NW) s_warp[lane] = wv;
    }
    __syncthreads();
    unsigned long long incl = v + (warp > 0 ? s_warp[warp - 1] : 0ull);
    unsigned long long total = s_warp[NW - 1];
    const long long G = (long long)(unsigned)(total >> 32);

    double acc = 0.0;
    if (cnt) {
        long long n  = (long long)(unsigned)(incl & 0xffffffffu);
        long long ss = (long long)(unsigned)(incl >> 32);
        long long np = n - (long long)cnt;
        long long sp = ss - (long long)fgc;
        long long u1 = G + n - ss;       // union after this bin
        long long u0 = G + np - sp;      // union before this bin
        float dJ;
        if (u0 == 0) {
            dJ = 1.0f;                   // G==0, first nonempty bin: J 0 -> 1
        } else {
            long long num = (G - sp) * u1 - (G - ss) * u0;  // exact int64
            dJ = (float)num / ((float)u1 * (float)u0);
        }
        float e_mid = ((float)bin + 0.5f) * (1.0f / (float)NB);
        acc = (double)(e_mid * dJ);
    }

    // block reduce (doubles)
    for (int o = 16; o; o >>= 1) acc += __shfl_down_sync(0xffffffffu, acc, o);
    if (lane == 0) s_red[warp] = acc;
    __syncthreads();
    if (warp == 0) {
        double a = (lane < NW) ? s_red[lane] : 0.0;
        for (int o = 2; o; o >>= 1) a += __shfl_down_sync(0xffffffffu, a, o);
        if (lane == 0) g_class_loss[c] = a;
    }
}

// ---------------------------------------------------------------------------
// Kernel 3: deterministic final mean over classes
// ---------------------------------------------------------------------------
__global__ void sum_kernel(float* d_out) {
    if (threadIdx.x == 0 && blockIdx.x == 0) {
        double s = 0.0;
        for (int c = 0; c < Cn; c++) s += g_class_loss[c];
        *d_out = (float)(s / (double)Cn);   // LOSS_WEIGHT = 1.0
    }
}

// ---------------------------------------------------------------------------
extern "C" void kernel_launch(void* const* d_in, const int* in_sizes, int n_in,
                              void* d_out, int out_size) {
    const float* inputs = (const float*)d_in[0];   // [8,21,512,512] f32
    const int* targets = (const int*)d_in[1];      // [8,512,512] int32
    float* out = (float*)d_out;

    zero_kernel<<<21, 128>>>(out);
    hist_kernel<<<HBLK, TPB>>>(inputs, targets);
    finalize_kernel<<<Cn, NB>>>();
    sum_kernel<<<1, 32>>>(out);
}